// round 11
// baseline (speedup 1.0000x reference)
#include <cuda_runtime.h>

#define BN   256
#define RN   2048
#define NCAP 10
#define OD   16
#define IND  8
#define NO   (NCAP * OD)   // 160

// 335 MB scratch for u_hat[b][r][o], o in [0,160)
__device__ float g_uhat[(size_t)BN * RN * NO];

// ---------------------------------------------------------------------------
// Kernel 1: u_hat[b,r,o] = sum_i x[b,r,i] * W[r,i,o]
// One CTA per r. Each lane keeps its 8x5 slice of W[r] in registers and
// reuses it across all 256 batch rows. x broadcast via shfl.
// ---------------------------------------------------------------------------
__global__ void __launch_bounds__(512)
uhat_kernel(const float* __restrict__ x,
            const float* __restrict__ W) {
    const int r    = blockIdx.x;
    const int lane = threadIdx.x & 31;
    const int warp = threadIdx.x >> 5;
    const int nw   = blockDim.x >> 5;

    // Preload W[r, :, lane + 32k]
    float wreg[IND][5];
#pragma unroll
    for (int i = 0; i < IND; ++i)
#pragma unroll
        for (int k = 0; k < 5; ++k)
            wreg[i][k] = W[((size_t)r * IND + i) * NO + lane + 32 * k];

    for (int b = warp; b < BN; b += nw) {
        float xv = 0.0f;
        if (lane < IND) xv = x[((size_t)b * RN + r) * IND + lane];

        float u[5] = {0.f, 0.f, 0.f, 0.f, 0.f};
#pragma unroll
        for (int i = 0; i < IND; ++i) {
            float xi = __shfl_sync(0xffffffffu, xv, i);
#pragma unroll
            for (int k = 0; k < 5; ++k)
                u[k] = fmaf(xi, wreg[i][k], u[k]);
        }
        size_t base = ((size_t)b * RN + r) * (size_t)NO + lane;
#pragma unroll
        for (int k = 0; k < 5; ++k)
            __stcs(&g_uhat[base + 32 * k], u[k]);   // streaming store: no reuse
    }
}

// ---------------------------------------------------------------------------
// Kernel 2: full dynamic routing for one batch element per CTA.
//   bB[2048][10] lives in SMEM. Iteration 0: c = softmax(b), s, v.
//   Iterations 1..3: bB += dot(u_hat, v); c = softmax(bB); s; v.
//   Writes c (last softmax) and v (last squash) to the output.
// Lane owns o = lane + 32k (k = 0..4); capsule n = o>>4 = 2k + (lane>>4).
// ---------------------------------------------------------------------------
__global__ void __launch_bounds__(512)
route_kernel(const float* __restrict__ blog,
             const float* __restrict__ uhat_g,
             float* __restrict__ outv,
             float* __restrict__ outc) {
    extern __shared__ float sm[];
    float* bB       = sm;                 // RN*NCAP = 20480 floats
    float* s_sh     = bB + RN * NCAP;     // 160
    float* vsh      = s_sh + NO;          // 160
    float* scale_sh = vsh + NO;           // 16

    const int b    = blockIdx.x;
    const int tid  = threadIdx.x;
    const int lane = tid & 31;
    const int warp = tid >> 5;
    const int nw   = blockDim.x >> 5;
    const int half = lane >> 4;           // 0 for lanes 0-15, 1 for 16-31

    // init SMEM state
    for (int i = tid; i < RN * NCAP; i += blockDim.x) bB[i] = blog[i];
    if (tid < NO) s_sh[tid] = 0.0f;
    __syncthreads();

    float vreg[5], sAcc[5];
#pragma unroll
    for (int k = 0; k < 5; ++k) { vreg[k] = 0.0f; sAcc[k] = 0.0f; }

    const float* uh   = uhat_g + (size_t)b * RN * NO;
    const int   tasks = RN / nw;   // 2048/16 = 128

    for (int iter = 0; iter <= 3; ++iter) {
        const bool agree = (iter > 0);
        const bool wC    = (iter == 3);

        int r = warp;
        float u[5];
        {
            const float* p = uh + (size_t)r * NO + lane;
#pragma unroll
            for (int k = 0; k < 5; ++k) u[k] = __ldcs(&p[32 * k]);
        }

        for (int t = 0; t < tasks; ++t) {
            const int rn = r + nw;
            float un[5];
            if (t + 1 < tasks) {               // prefetch next row's u_hat
                const float* p = uh + (size_t)rn * NO + lane;
#pragma unroll
                for (int k = 0; k < 5; ++k) un[k] = __ldcs(&p[32 * k]);
            } else {
#pragma unroll
                for (int k = 0; k < 5; ++k) un[k] = 0.0f;
            }

            if (agree) {
                // agreement a[n] = sum over the 16 o's of capsule n of u*v
#pragma unroll
                for (int k = 0; k < 5; ++k) {
                    float p = u[k] * vreg[k];
                    p += __shfl_xor_sync(0xffffffffu, p, 8);
                    p += __shfl_xor_sync(0xffffffffu, p, 4);
                    p += __shfl_xor_sync(0xffffffffu, p, 2);
                    p += __shfl_xor_sync(0xffffffffu, p, 1);
                    if (lane == 0 || lane == 16)
                        bB[r * NCAP + 2 * k + half] += p;
                }
                __syncwarp();
            }

            // softmax over the 10 capsule classes of this row
            float val = (lane < NCAP) ? bB[r * NCAP + lane] : -1e30f;
            float m = val;
            m = fmaxf(m, __shfl_xor_sync(0xffffffffu, m, 16));
            m = fmaxf(m, __shfl_xor_sync(0xffffffffu, m, 8));
            m = fmaxf(m, __shfl_xor_sync(0xffffffffu, m, 4));
            m = fmaxf(m, __shfl_xor_sync(0xffffffffu, m, 2));
            m = fmaxf(m, __shfl_xor_sync(0xffffffffu, m, 1));
            float e = (lane < NCAP) ? __expf(val - m) : 0.0f;
            float ssum = e;
            ssum += __shfl_xor_sync(0xffffffffu, ssum, 16);
            ssum += __shfl_xor_sync(0xffffffffu, ssum, 8);
            ssum += __shfl_xor_sync(0xffffffffu, ssum, 4);
            ssum += __shfl_xor_sync(0xffffffffu, ssum, 2);
            ssum += __shfl_xor_sync(0xffffffffu, ssum, 1);
            float c = e * __frcp_rn(ssum);   // valid on lanes 0..9

            if (wC && outc != nullptr && lane < NCAP)
                outc[((size_t)b * RN + r) * NCAP + lane] = c;

            // s accumulation: sAcc[o] += c[n] * u_hat[o]
#pragma unroll
            for (int k = 0; k < 5; ++k) {
                float ck = __shfl_sync(0xffffffffu, c, 2 * k + half);
                sAcc[k] = fmaf(ck, u[k], sAcc[k]);
            }

#pragma unroll
            for (int k = 0; k < 5; ++k) u[k] = un[k];
            r = rn;
        }

        // cross-warp reduction of s, then squash -> v
#pragma unroll
        for (int k = 0; k < 5; ++k)
            atomicAdd(&s_sh[lane + 32 * k], sAcc[k]);
        __syncthreads();

        if (tid < NCAP) {
            float n2 = 0.0f;
#pragma unroll
            for (int j = 0; j < OD; ++j) {
                float sv = s_sh[tid * OD + j];
                n2 = fmaf(sv, sv, n2);
            }
            scale_sh[tid] = sqrtf(n2) / (1.0f + n2 + 1e-8f);
        }
        __syncthreads();
        if (tid < NO) vsh[tid] = scale_sh[tid >> 4] * s_sh[tid];
        __syncthreads();
#pragma unroll
        for (int k = 0; k < 5; ++k) {
            vreg[k] = vsh[lane + 32 * k];
            sAcc[k] = 0.0f;
        }
        if (tid < NO) s_sh[tid] = 0.0f;
        __syncthreads();
    }

    // final v (output order: v first, then c)
    if (tid < NO) outv[(size_t)b * NO + tid] = vsh[tid];
}

// ---------------------------------------------------------------------------
extern "C" void kernel_launch(void* const* d_in, const int* in_sizes, int n_in,
                              void* d_out, int out_size) {
    const float* x    = (const float*)d_in[0];   // [256, 2048, 8]
    const float* W    = (const float*)d_in[1];   // [2048, 8, 160]
    const float* blog = (const float*)d_in[2];   // [2048, 10]

    float* out  = (float*)d_out;
    float* outv = out;                            // v: [256, 10, 16] = 40960
    float* outc = nullptr;                        // c: [256, 2048, 10] = 5242880
    const long long vElems = (long long)BN * NO;
    const long long cElems = (long long)BN * RN * NCAP;
    if ((long long)out_size >= vElems + cElems) outc = out + vElems;

    uhat_kernel<<<RN, 512>>>(x, W);

    const size_t smem = (size_t)(RN * NCAP + 2 * NO + 16) * sizeof(float); // 83264 B
    cudaFuncSetAttribute(route_kernel,
                         cudaFuncAttributeMaxDynamicSharedMemorySize,
                         (int)smem);
    void* uhat_ptr = nullptr;
    cudaGetSymbolAddress(&uhat_ptr, g_uhat);
    route_kernel<<<BN, 512, smem>>>(blog, (const float*)uhat_ptr, outv, outc);
}